// round 7
// baseline (speedup 1.0000x reference)
#include <cuda_runtime.h>
#include <cuda_bf16.h>
#include <math.h>

// ---------------------------------------------------------------------------
// dsq_loss: loss = nanmean |log10(Dsq(target)) - log10(Dsq(pred))|
// Dsq built from radially-binned power spectrum of 128^3 fields, batch=8.
//
// Pipeline (all graph-capturable, no allocations):
//   k_setup   : fp64 replica of numpy binning -> bin_of_m table, kcent; zero sums
//   k_fft_zy  : Z = pred + i*target; fused z-FFT + y-FFT per x-slice (shared plane)
//   k_fft_x   : x-FFT on 128x32 tiles
//   k_bin     : Hermitian split |Fp|^2,|Ft|^2 -> per-bin sums (f32 shared, f64 global)
//   k_final   : replicate reference fp32 formula + nanmean
// ---------------------------------------------------------------------------

#define NSIDE 128
#define NMODES (128*128*128)        // 2,097,152
#define NBATCH 8
#define KBINS 100
#define MMAX 12288                  // 3*64^2

// 128 MB complex scratch (static device global: allowed)
__device__ float2 g_vol[(size_t)NBATCH * NMODES];
__device__ double g_SP[NBATCH * KBINS];
__device__ double g_ST[NBATCH * KBINS];
__device__ int    g_CNT[KBINS];
__device__ unsigned char g_binm[MMAX + 1];
__device__ float  g_kcent[KBINS];

__device__ __forceinline__ int rev7(int x) {
    return (int)(__brev((unsigned)x) >> 25);
}

// ---------------------------------------------------------------------------
// radix-2 DIF butterfly: a <- a+b ; b <- (a-b)*w
// ---------------------------------------------------------------------------
__device__ __forceinline__ void bfly(float& ar, float& ai, float& br, float& bi,
                                     float wr, float wi) {
    float ur = ar, ui = ai;
    ar = ur + br; ai = ui + bi;
    float dr = ur - br, di = ui - bi;
    br = dr * wr - di * wi;
    bi = dr * wi + di * wr;
}

// full 16-point DIF in registers, constant twiddles (stages len=16,8,4,2)
__device__ __forceinline__ void fft16(float xr[16], float xi[16]) {
    const float C1 = 0.92387953251128674f;   // cos(pi/8)
    const float S1 = 0.38268343236508978f;   // sin(pi/8)
    const float C2 = 0.70710678118654752f;   // sqrt(2)/2
    const float W16r[8] = {1.f,  C1,  C2,  S1, 0.f, -S1, -C2, -C1};
    const float W16i[8] = {0.f, -S1, -C2, -C1, -1.f, -C1, -C2, -S1};
#pragma unroll
    for (int j = 0; j < 8; j++)
        bfly(xr[j], xi[j], xr[j + 8], xi[j + 8], W16r[j], W16i[j]);
    const float W8r[4] = {1.f,  C2, 0.f, -C2};
    const float W8i[4] = {0.f, -C2, -1.f, -C2};
#pragma unroll
    for (int g = 0; g < 16; g += 8)
#pragma unroll
        for (int j = 0; j < 4; j++)
            bfly(xr[g + j], xi[g + j], xr[g + j + 4], xi[g + j + 4], W8r[j], W8i[j]);
#pragma unroll
    for (int g = 0; g < 16; g += 4) {
        bfly(xr[g],     xi[g],     xr[g + 2], xi[g + 2], 1.f,  0.f);
        bfly(xr[g + 1], xi[g + 1], xr[g + 3], xi[g + 3], 0.f, -1.f);
    }
#pragma unroll
    for (int g = 0; g < 16; g += 2)
        bfly(xr[g], xi[g], xr[g + 1], xi[g + 1], 1.f, 0.f);
}

// ---------------------------------------------------------------------------
// 128-point DIF FFT on LINES lines living in shared memory.
// Element stride ES along a line, line stride LS. Output bit-reversed in place.
// Phase 1: 16 threads/line hold 8 points (stride 16) -> 3 register stages
//          (len=128,64,32) with twiddles from shared W128 table.
// Phase 2: 8 threads/line each own a contiguous 16-block -> full fft16.
// Thread mapping line = s % LINES keeps all shared accesses conflict-free
// for all three (ES,LS) instantiations used here.
// ---------------------------------------------------------------------------
template <int LINES, int ES, int LS>
__device__ __forceinline__ void fft_lines(float* sRe, float* sIm,
                                          const float* wRe, const float* wIm,
                                          int tid, int nt) {
    for (int s = tid; s < LINES * 16; s += nt) {
        int line = s & (LINES - 1);
        int t = s / LINES;                 // 0..15
        int base = line * LS;
        float vr[8], vi[8];
#pragma unroll
        for (int r = 0; r < 8; r++) {
            int idx = base + (t + 16 * r) * ES;
            vr[r] = sRe[idx]; vi[r] = sIm[idx];
        }
        // stage len=128: pairs (i, i+64), tw W128^i, i = t+16r (r<4)
#pragma unroll
        for (int r = 0; r < 4; r++) {
            int j = t + 16 * r;
            bfly(vr[r], vi[r], vr[r + 4], vi[r + 4], wRe[j], wIm[j]);
        }
        // stage len=64: groups {0,64}; tw W128^{2(t+16r)}, r<2
#pragma unroll
        for (int q = 0; q < 8; q += 4)
#pragma unroll
            for (int r = 0; r < 2; r++) {
                int j = 2 * (t + 16 * r);
                bfly(vr[q + r], vi[q + r], vr[q + r + 2], vi[q + r + 2], wRe[j], wIm[j]);
            }
        // stage len=32: tw W128^{4t}
        {
            int j = 4 * t;
            float cw = wRe[j], sw = wIm[j];
#pragma unroll
            for (int q = 0; q < 8; q += 2)
                bfly(vr[q], vi[q], vr[q + 1], vi[q + 1], cw, sw);
        }
#pragma unroll
        for (int r = 0; r < 8; r++) {
            int idx = base + (t + 16 * r) * ES;
            sRe[idx] = vr[r]; sIm[idx] = vi[r];
        }
    }
    __syncthreads();
    for (int s = tid; s < LINES * 8; s += nt) {
        int line = s & (LINES - 1);
        int blk = s / LINES;               // 0..7
        int base = line * LS + blk * 16 * ES;
        float xr[16], xi[16];
#pragma unroll
        for (int j = 0; j < 16; j++) {
            int idx = base + j * ES;
            xr[j] = sRe[idx]; xi[j] = sIm[idx];
        }
        fft16(xr, xi);
#pragma unroll
        for (int j = 0; j < 16; j++) {
            int idx = base + j * ES;
            sRe[idx] = xr[j]; sIm[idx] = xi[j];
        }
    }
    __syncthreads();
}

// ---------------------------------------------------------------------------
// Setup: replicate numpy binning bit-exactly in fp64 (fma-free), build
// bin_of_m lookup, kcent; zero accumulators.
// ---------------------------------------------------------------------------
__global__ void k_setup() {
    __shared__ double edges[KBINS + 1];
    int tid = threadIdx.x;
    const double TWO_PI = 6.283185307179586476925286766559;
    double val = 1.0 / 384.0;                                   // 1/(n*d)
    double k1  = __dmul_rn(TWO_PI, __dmul_rn(1.0, val));        // kf[1]
    double csq = __dmul_rn(k1, k1);
    double kmin = sqrt(csq);                                    // kmag(1,0,0)
    double k64 = __dmul_rn(TWO_PI, __dmul_rn(64.0, val));       // |kf[64]|
    double q64 = __dmul_rn(k64, k64);
    double kmax = sqrt(__dadd_rn(__dadd_rn(q64, q64), q64));    // kmag(64,64,64)
    double step = __dmul_rn(__dadd_rn(kmax, -kmin), 1.0) / 100.0;
    // np.linspace: edges[i] = i*step + start ; edges[100] = stop
    if (tid <= KBINS) {
        double e = (tid == KBINS) ? kmax
                                  : __dadd_rn(__dmul_rn((double)tid, step), kmin);
        edges[tid] = e;
    }
    __syncthreads();
    if (tid < KBINS)
        g_kcent[tid] = (float)(0.5 * __dadd_rn(edges[tid], edges[tid + 1]));
    for (int m = tid; m <= MMAX; m += blockDim.x) {
        unsigned char bm;
        if (m == 0) {
            bm = 255;                       // DC -> dropped bin
        } else {
            double km = sqrt(__dmul_rn((double)m, csq));
            // searchsorted(edges, km, side='right')
            int lo = 0, hi = KBINS + 1;
            while (lo < hi) {
                int mid = (lo + hi) >> 1;
                if (edges[mid] <= km) lo = mid + 1; else hi = mid;
            }
            int bin = lo - 1;
            bin = bin < 0 ? 0 : (bin > KBINS - 1 ? KBINS - 1 : bin);
            bm = (unsigned char)bin;
        }
        g_binm[m] = bm;
    }
    for (int i = tid; i < NBATCH * KBINS; i += blockDim.x) {
        g_SP[i] = 0.0; g_ST[i] = 0.0;
    }
    if (tid < KBINS) g_CNT[tid] = 0;
}

// ---------------------------------------------------------------------------
// Kernel 1: load plane (y,z) of Z = pred + i*target, z-FFT then y-FFT, store.
// grid (128 x-slices, 8 batches), 512 threads, 132 KB dynamic shared.
// ---------------------------------------------------------------------------
#define PITCH1 129
__global__ void k_fft_zy(const float* __restrict__ pred,
                         const float* __restrict__ targ) {
    extern __shared__ float smem[];
    float* sRe = smem;
    float* sIm = smem + NSIDE * PITCH1;
    __shared__ float wRe[64], wIm[64];
    int tid = threadIdx.x;
    int x = blockIdx.x, b = blockIdx.y;
    if (tid < 64) {
        float s, c;
        sincospif(-(float)tid / 64.0f, &s, &c);   // exp(-2*pi*i*t/128)
        wRe[tid] = c; wIm[tid] = s;
    }
    const float* p = pred + ((size_t)b * NSIDE + x) * (NSIDE * NSIDE);
    const float* t = targ + ((size_t)b * NSIDE + x) * (NSIDE * NSIDE);
    for (int i = tid; i < NSIDE * NSIDE; i += blockDim.x) {
        int y = i >> 7, z = i & 127;
        sRe[y * PITCH1 + z] = p[i];
        sIm[y * PITCH1 + z] = t[i];
    }
    __syncthreads();
    fft_lines<128, 1, PITCH1>(sRe, sIm, wRe, wIm, tid, blockDim.x);  // z
    fft_lines<128, PITCH1, 1>(sRe, sIm, wRe, wIm, tid, blockDim.x);  // y
    float2* o = g_vol + ((size_t)b * NSIDE + x) * (NSIDE * NSIDE);
    for (int i = tid; i < NSIDE * NSIDE; i += blockDim.x) {
        int y = i >> 7, z = i & 127;
        o[i] = make_float2(sRe[y * PITCH1 + z], sIm[y * PITCH1 + z]);
    }
}

// ---------------------------------------------------------------------------
// Kernel 2: x-FFT on tiles of (x=128, z-chunk=32) at fixed (b, y).
// grid (128*4, 8), 256 threads, ~34 KB static shared.
// ---------------------------------------------------------------------------
#define PITCH2 33
__global__ void k_fft_x() {
    __shared__ float sRe[NSIDE * PITCH2], sIm[NSIDE * PITCH2];
    __shared__ float wRe[64], wIm[64];
    int tid = threadIdx.x;
    int b = blockIdx.y;
    int y = blockIdx.x >> 2;
    int zc = (blockIdx.x & 3) * 32;
    if (tid < 64) {
        float s, c;
        sincospif(-(float)tid / 64.0f, &s, &c);
        wRe[tid] = c; wIm[tid] = s;
    }
    float2* vol = g_vol + (size_t)b * NMODES;
    for (int i = tid; i < 128 * 32; i += blockDim.x) {
        int xi = i >> 5, zi = i & 31;
        float2 v = vol[((size_t)xi << 14) + (y << 7) + zc + zi];
        sRe[xi * PITCH2 + zi] = v.x;
        sIm[xi * PITCH2 + zi] = v.y;
    }
    __syncthreads();
    fft_lines<32, PITCH2, 1>(sRe, sIm, wRe, wIm, tid, blockDim.x);   // x
    for (int i = tid; i < 128 * 32; i += blockDim.x) {
        int xi = i >> 5, zi = i & 31;
        vol[((size_t)xi << 14) + (y << 7) + zc + zi] =
            make_float2(sRe[xi * PITCH2 + zi], sIm[xi * PITCH2 + zi]);
    }
}

// ---------------------------------------------------------------------------
// Kernel 3: Hermitian split + radial binning.
// Stored index s holds F(rev7(sx),rev7(sy),rev7(sz)) of Z = pred + i*target.
// |Fp(f)|^2 = (|Z(f)|^2+|Z(-f)|^2+2Re(Z(f)Z(-f)))/4 ; |Ft| with minus.
// grid (512, 8), 256 threads, 4096 modes/block.
// ---------------------------------------------------------------------------
__global__ void k_bin() {
    __shared__ float shP[KBINS], shT[KBINS];
    __shared__ int shC[KBINS];
    __shared__ unsigned char shB[MMAX + 1];
    int tid = threadIdx.x;
    int b = blockIdx.y;
    if (tid < KBINS) { shP[tid] = 0.f; shT[tid] = 0.f; shC[tid] = 0; }
    for (int i = tid; i <= MMAX; i += blockDim.x) shB[i] = g_binm[i];
    __syncthreads();
    const float2* vol = g_vol + (size_t)b * NMODES;
    int base = blockIdx.x * 4096;
#pragma unroll 4
    for (int it = 0; it < 16; it++) {
        int s = base + it * 256 + tid;
        int sx = s >> 14, sy = (s >> 7) & 127, sz = s & 127;
        int fx = rev7(sx), fy = rev7(sy), fz = rev7(sz);
        int ax = min(fx, 128 - fx), ay = min(fy, 128 - fy), az = min(fz, 128 - fz);
        int m = ax * ax + ay * ay + az * az;
        float2 z1 = vol[s];
        int s2 = (rev7((128 - fx) & 127) << 14) |
                 (rev7((128 - fy) & 127) << 7) |
                  rev7((128 - fz) & 127);
        float2 z2 = vol[s2];
        if (m) {
            float aa = z1.x * z1.x + z1.y * z1.y;
            float bb = z2.x * z2.x + z2.y * z2.y;
            float cr = z1.x * z2.x - z1.y * z2.y;   // Re(Z1*Z2)
            float h = 0.25f * (aa + bb);
            float pv = h + 0.5f * cr;
            float tv = h - 0.5f * cr;
            int bin = shB[m];
            atomicAdd(&shP[bin], pv);
            atomicAdd(&shT[bin], tv);
            if (b == 0) atomicAdd(&shC[bin], 1);
        }
    }
    __syncthreads();
    if (tid < KBINS) {
        atomicAdd(&g_SP[b * KBINS + tid], (double)shP[tid]);
        atomicAdd(&g_ST[b * KBINS + tid], (double)shT[tid]);
        if (b == 0) atomicAdd(&g_CNT[tid], shC[tid]);
    }
}

// ---------------------------------------------------------------------------
// Final: replicate reference fp32 formula per (b, bin) and nanmean.
// ---------------------------------------------------------------------------
__global__ void k_final(float* out) {
    __shared__ float red[256];
    __shared__ int redn[256];
    int tid = threadIdx.x;
    const float PKF = 27.0f / 2097152.0f;            // Lpix^3 / N^3
    const float TWOPI2 = 19.739208802178716f;        // 2*pi^2
    float local = 0.f;
    int ln = 0;
    for (int i = tid; i < NBATCH * KBINS; i += 256) {
        int bin = i % KBINS;
        int c = g_CNT[bin];
        if (c > 0) {
            float cf = (float)c;
            float kc = g_kcent[bin];
            float kc3 = kc * kc * kc;
            float sp = (float)g_SP[i] * PKF;
            float st = (float)g_ST[i] * PKF;
            float dp = (sp / cf) * kc3 / TWOPI2;
            float dt = (st / cf) * kc3 / TWOPI2;
            local += fabsf(log10f(dt) - log10f(dp));
            ln++;
        }
    }
    red[tid] = local; redn[tid] = ln;
    __syncthreads();
    for (int s = 128; s > 0; s >>= 1) {
        if (tid < s) { red[tid] += red[tid + s]; redn[tid] += redn[tid + s]; }
        __syncthreads();
    }
    if (tid == 0) out[0] = red[0] / (float)redn[0];
}

// ---------------------------------------------------------------------------
extern "C" void kernel_launch(void* const* d_in, const int* in_sizes, int n_in,
                              void* d_out, int out_size) {
    const float* pred = (const float*)d_in[0];
    const float* targ = (const float*)d_in[1];
    float* out = (float*)d_out;

    const int SMEM_ZY = 2 * NSIDE * PITCH1 * (int)sizeof(float);  // 132096 B
    cudaFuncSetAttribute(k_fft_zy, cudaFuncAttributeMaxDynamicSharedMemorySize,
                         SMEM_ZY);

    k_setup<<<1, 256>>>();
    k_fft_zy<<<dim3(NSIDE, NBATCH), 512, SMEM_ZY>>>(pred, targ);
    k_fft_x<<<dim3(NSIDE * 4, NBATCH), 256>>>();
    k_bin<<<dim3(512, NBATCH), 256>>>();
    k_final<<<1, 256>>>(out);
}

// round 12
// speedup vs baseline: 1.5373x; 1.5373x over previous
#include <cuda_runtime.h>
#include <cuda_bf16.h>
#include <math.h>

// ---------------------------------------------------------------------------
// dsq_loss: loss = nanmean |log10(Dsq(target)) - log10(Dsq(pred))|
//
// Pipeline (graph-capturable, no allocations):
//   k_setup     : fp64 replica of numpy binning -> bin_of_m table, kcent; zero sums
//   k_fft_zy    : Z = pred + i*target; fused z-FFT + y-FFT per x-slice
//   k_fft_x_bin : x-FFT on mirror-closed (y-pair, z-half) planes + in-shared
//                 Hermitian split + radial binning (pair-once, weight 2)
//   k_final     : replicate reference fp32 formula + nanmean
// ---------------------------------------------------------------------------

#define NSIDE 128
#define NMODES (128*128*128)
#define NBATCH 8
#define KBINS 100
#define MMAX 12288                  // 3*64^2

__device__ float2 g_vol[(size_t)NBATCH * NMODES];   // 128 MB scratch
__device__ double g_SP[NBATCH * KBINS];
__device__ double g_ST[NBATCH * KBINS];
__device__ int    g_CNT[KBINS];
__device__ unsigned char g_binm[MMAX + 1];
__device__ float  g_kcent[KBINS];

__device__ __forceinline__ int rev7(int x) {
    return (int)(__brev((unsigned)x) >> 25);
}

// radix-2 DIF butterfly: a <- a+b ; b <- (a-b)*w
__device__ __forceinline__ void bfly(float& ar, float& ai, float& br, float& bi,
                                     float wr, float wi) {
    float ur = ar, ui = ai;
    ar = ur + br; ai = ui + bi;
    float dr = ur - br, di = ui - bi;
    br = dr * wr - di * wi;
    bi = dr * wi + di * wr;
}

// full 16-point DIF in registers, constant twiddles
__device__ __forceinline__ void fft16(float xr[16], float xi[16]) {
    const float C1 = 0.92387953251128674f;
    const float S1 = 0.38268343236508978f;
    const float C2 = 0.70710678118654752f;
    const float W16r[8] = {1.f,  C1,  C2,  S1, 0.f, -S1, -C2, -C1};
    const float W16i[8] = {0.f, -S1, -C2, -C1, -1.f, -C1, -C2, -S1};
#pragma unroll
    for (int j = 0; j < 8; j++)
        bfly(xr[j], xi[j], xr[j + 8], xi[j + 8], W16r[j], W16i[j]);
    const float W8r[4] = {1.f,  C2, 0.f, -C2};
    const float W8i[4] = {0.f, -C2, -1.f, -C2};
#pragma unroll
    for (int g = 0; g < 16; g += 8)
#pragma unroll
        for (int j = 0; j < 4; j++)
            bfly(xr[g + j], xi[g + j], xr[g + j + 4], xi[g + j + 4], W8r[j], W8i[j]);
#pragma unroll
    for (int g = 0; g < 16; g += 4) {
        bfly(xr[g],     xi[g],     xr[g + 2], xi[g + 2], 1.f,  0.f);
        bfly(xr[g + 1], xi[g + 1], xr[g + 3], xi[g + 3], 0.f, -1.f);
    }
#pragma unroll
    for (int g = 0; g < 16; g += 2)
        bfly(xr[g], xi[g], xr[g + 1], xi[g + 1], 1.f, 0.f);
}

// 128-point DIF FFT on LINES lines in shared memory, bit-reversed output.
template <int LINES, int ES, int LS>
__device__ __forceinline__ void fft_lines(float* sRe, float* sIm,
                                          const float* wRe, const float* wIm,
                                          int tid, int nt) {
    for (int s = tid; s < LINES * 16; s += nt) {
        int line = s & (LINES - 1);
        int t = s / LINES;
        int base = line * LS;
        float vr[8], vi[8];
#pragma unroll
        for (int r = 0; r < 8; r++) {
            int idx = base + (t + 16 * r) * ES;
            vr[r] = sRe[idx]; vi[r] = sIm[idx];
        }
#pragma unroll
        for (int r = 0; r < 4; r++) {
            int j = t + 16 * r;
            bfly(vr[r], vi[r], vr[r + 4], vi[r + 4], wRe[j], wIm[j]);
        }
#pragma unroll
        for (int q = 0; q < 8; q += 4)
#pragma unroll
            for (int r = 0; r < 2; r++) {
                int j = 2 * (t + 16 * r);
                bfly(vr[q + r], vi[q + r], vr[q + r + 2], vi[q + r + 2], wRe[j], wIm[j]);
            }
        {
            int j = 4 * t;
            float cw = wRe[j], sw = wIm[j];
#pragma unroll
            for (int q = 0; q < 8; q += 2)
                bfly(vr[q], vi[q], vr[q + 1], vi[q + 1], cw, sw);
        }
#pragma unroll
        for (int r = 0; r < 8; r++) {
            int idx = base + (t + 16 * r) * ES;
            sRe[idx] = vr[r]; sIm[idx] = vi[r];
        }
    }
    __syncthreads();
    for (int s = tid; s < LINES * 8; s += nt) {
        int line = s & (LINES - 1);
        int blk = s / LINES;
        int base = line * LS + blk * 16 * ES;
        float xr[16], xi[16];
#pragma unroll
        for (int j = 0; j < 16; j++) {
            int idx = base + j * ES;
            xr[j] = sRe[idx]; xi[j] = sIm[idx];
        }
        fft16(xr, xi);
#pragma unroll
        for (int j = 0; j < 16; j++) {
            int idx = base + j * ES;
            sRe[idx] = xr[j]; sIm[idx] = xi[j];
        }
    }
    __syncthreads();
}

// ---------------------------------------------------------------------------
// Setup: numpy binning bit-exact in fp64 (fma-free), bin_of_m lookup, kcent.
// ---------------------------------------------------------------------------
__global__ void k_setup() {
    __shared__ double edges[KBINS + 1];
    int tid = threadIdx.x;
    const double TWO_PI = 6.283185307179586476925286766559;
    double val = 1.0 / 384.0;
    double k1  = __dmul_rn(TWO_PI, __dmul_rn(1.0, val));
    double csq = __dmul_rn(k1, k1);
    double kmin = sqrt(csq);
    double k64 = __dmul_rn(TWO_PI, __dmul_rn(64.0, val));
    double q64 = __dmul_rn(k64, k64);
    double kmax = sqrt(__dadd_rn(__dadd_rn(q64, q64), q64));
    double step = __dmul_rn(__dadd_rn(kmax, -kmin), 1.0) / 100.0;
    if (tid <= KBINS) {
        double e = (tid == KBINS) ? kmax
                                  : __dadd_rn(__dmul_rn((double)tid, step), kmin);
        edges[tid] = e;
    }
    __syncthreads();
    if (tid < KBINS)
        g_kcent[tid] = (float)(0.5 * __dadd_rn(edges[tid], edges[tid + 1]));
    for (int m = tid; m <= MMAX; m += blockDim.x) {
        unsigned char bm;
        if (m == 0) {
            bm = 255;
        } else {
            double km = sqrt(__dmul_rn((double)m, csq));
            int lo = 0, hi = KBINS + 1;
            while (lo < hi) {
                int mid = (lo + hi) >> 1;
                if (edges[mid] <= km) lo = mid + 1; else hi = mid;
            }
            int bin = lo - 1;
            bin = bin < 0 ? 0 : (bin > KBINS - 1 ? KBINS - 1 : bin);
            bm = (unsigned char)bin;
        }
        g_binm[m] = bm;
    }
    for (int i = tid; i < NBATCH * KBINS; i += blockDim.x) {
        g_SP[i] = 0.0; g_ST[i] = 0.0;
    }
    if (tid < KBINS) g_CNT[tid] = 0;
}

// ---------------------------------------------------------------------------
// Kernel 1: plane (y,z) of Z = pred + i*target, z-FFT then y-FFT, store.
// ---------------------------------------------------------------------------
#define PITCH1 129
__global__ void k_fft_zy(const float* __restrict__ pred,
                         const float* __restrict__ targ) {
    extern __shared__ float smem[];
    float* sRe = smem;
    float* sIm = smem + NSIDE * PITCH1;
    __shared__ float wRe[64], wIm[64];
    int tid = threadIdx.x;
    int x = blockIdx.x, b = blockIdx.y;
    if (tid < 64) {
        float s, c;
        sincospif(-(float)tid / 64.0f, &s, &c);
        wRe[tid] = c; wIm[tid] = s;
    }
    const float* p = pred + ((size_t)b * NSIDE + x) * (NSIDE * NSIDE);
    const float* t = targ + ((size_t)b * NSIDE + x) * (NSIDE * NSIDE);
    for (int i = tid; i < NSIDE * NSIDE; i += blockDim.x) {
        int y = i >> 7, z = i & 127;
        sRe[y * PITCH1 + z] = p[i];
        sIm[y * PITCH1 + z] = t[i];
    }
    __syncthreads();
    fft_lines<128, 1, PITCH1>(sRe, sIm, wRe, wIm, tid, blockDim.x);  // z
    fft_lines<128, PITCH1, 1>(sRe, sIm, wRe, wIm, tid, blockDim.x);  // y
    float2* o = g_vol + ((size_t)b * NSIDE + x) * (NSIDE * NSIDE);
    for (int i = tid; i < NSIDE * NSIDE; i += blockDim.x) {
        int y = i >> 7, z = i & 127;
        o[i] = make_float2(sRe[y * PITCH1 + z], sIm[y * PITCH1 + z]);
    }
}

// ---------------------------------------------------------------------------
// Kernel 2 (fused): x-FFT + Hermitian split + radial binning.
//
// Block = (batch, y-pair, z-half). In stored (bit-reversed) coordinates the
// mirror of index s is s ^ ((1<<hb(s))-1): it stays inside the same x-line,
// inside the same z-half [0,64)/[64,128), and maps y within its pair. So all
// mirror partners are resident in the 128-line shared plane; each unordered
// pair is binned once with weight 2 (pv(f) == pv(-f) exactly).
// ---------------------------------------------------------------------------
__global__ void k_fft_x_bin() {
    extern __shared__ float smem[];
    float* sRe = smem;
    float* sIm = smem + NSIDE * PITCH1;
    __shared__ float wRe[64], wIm[64];
    __shared__ int   axsq[128];     // min(fx,128-fx)^2 indexed by stored sx
    __shared__ int   azsq[64];      // same for stored sz within this half
    __shared__ int   mxT[128];      // stored-x mirror
    __shared__ int   mzT[64];       // stored-z mirror (local to half)
    __shared__ unsigned char shB[MMAX + 1];
    __shared__ float shP[4 * KBINS], shT[4 * KBINS];
    __shared__ int   shC[KBINS];

    int tid = threadIdx.x;
    int nt = blockDim.x;
    int b = blockIdx.y;
    int g = blockIdx.x >> 1;        // y-group 0..63
    int h = blockIdx.x & 1;         // z-half

    // y-pair for this group
    int yA, yB, selfY;
    if (g == 0) { yA = 0; yB = 1; selfY = 1; }      // both self-mirrored
    else {
        int hb = 31 - __clz(g) + 1;                 // floor(log2(g)) + 1
        int r = g - (1 << (hb - 1));
        yA = (1 << hb) + r;
        yB = (1 << hb) + ((1 << hb) - 1 - r);
        selfY = 0;
    }
    int fyA = rev7(yA), fyB = rev7(yB);
    int aA = min(fyA, 128 - fyA), aB = min(fyB, 128 - fyB);
    int ay2A = aA * aA, ay2B = aB * aB;

    if (tid < 64) {
        float s, c;
        sincospif(-(float)tid / 64.0f, &s, &c);
        wRe[tid] = c; wIm[tid] = s;
    }
    if (tid < 128) {
        int f = rev7(tid), a = min(f, 128 - f);
        axsq[tid] = a * a;
        mxT[tid] = (tid == 0) ? 0 : (tid ^ ((1 << (31 - __clz(tid))) - 1));
    }
    if (tid < 64) {
        int sz = h * 64 + tid;
        int f = rev7(sz), a = min(f, 128 - f);
        azsq[tid] = a * a;
        int sz2 = (sz == 0) ? 0 : (sz ^ ((1 << (31 - __clz(sz))) - 1));
        mzT[tid] = sz2 - h * 64;    // mirror stays in the same half
    }
    for (int i = tid; i <= MMAX; i += nt) shB[i] = g_binm[i];
    for (int i = tid; i < 4 * KBINS; i += nt) { shP[i] = 0.f; shT[i] = 0.f; }
    if (tid < KBINS) shC[tid] = 0;

    // Load: lines l = yi*64 + zi, elements along x. Global reads are
    // 64-contiguous float2 runs; shared writes pitch-129 conflict-free.
    const float2* vol = g_vol + (size_t)b * NMODES;
    for (int i = tid; i < 128 * 128; i += nt) {
        int zi = i & 63;
        int yi = (i >> 6) & 1;
        int x  = i >> 7;
        int y  = yi ? yB : yA;
        float2 v = vol[((size_t)x << 14) + (y << 7) + h * 64 + zi];
        int l = yi * 64 + zi;
        sRe[l * PITCH1 + x] = v.x;
        sIm[l * PITCH1 + x] = v.y;
    }
    __syncthreads();

    fft_lines<128, 1, PITCH1>(sRe, sIm, wRe, wIm, tid, nt);   // x-FFT

    // Hermitian split + binning from shared (canonical pair once, weight 2)
    int rep = (tid & 3) * KBINS;
    for (int i = tid; i < 128 * 128; i += nt) {
        int sx = i & 127;
        int l  = i >> 7;
        int yi = l >> 6, zi = l & 63;
        int m = axsq[sx] + (yi ? ay2B : ay2A) + azsq[zi];
        if (m == 0) continue;                       // DC mode dropped
        int px  = mxT[sx];
        int pzi = mzT[zi];
        int pyi = selfY ? yi : (1 - yi);
        int key2 = (((pyi << 6) | pzi) << 7) | px;
        if (i > key2) continue;                     // partner handles it
        float w = (i == key2) ? 1.f : 2.f;
        float zr = sRe[l * PITCH1 + sx], zim = sIm[l * PITCH1 + sx];
        int pl = pyi * 64 + pzi;
        float qr = sRe[pl * PITCH1 + px], qi = sIm[pl * PITCH1 + px];
        float aa = zr * zr + zim * zim;
        float bb = qr * qr + qi * qi;
        float cr = zr * qr - zim * qi;              // Re(Z1*Z2)
        float hv = 0.25f * (aa + bb);
        int bin = shB[m];
        atomicAdd(&shP[rep + bin], w * (hv + 0.5f * cr));
        atomicAdd(&shT[rep + bin], w * (hv - 0.5f * cr));
        if (b == 0) atomicAdd(&shC[bin], (int)w);
    }
    __syncthreads();

    if (tid < KBINS) {
        float p = shP[tid] + shP[KBINS + tid] + shP[2 * KBINS + tid] + shP[3 * KBINS + tid];
        float t = shT[tid] + shT[KBINS + tid] + shT[2 * KBINS + tid] + shT[3 * KBINS + tid];
        atomicAdd(&g_SP[b * KBINS + tid], (double)p);
        atomicAdd(&g_ST[b * KBINS + tid], (double)t);
        if (b == 0) atomicAdd(&g_CNT[tid], shC[tid]);
    }
}

// ---------------------------------------------------------------------------
// Final: replicate reference fp32 formula per (b, bin) and nanmean.
// ---------------------------------------------------------------------------
__global__ void k_final(float* out) {
    __shared__ float red[256];
    __shared__ int redn[256];
    int tid = threadIdx.x;
    const float PKF = 27.0f / 2097152.0f;            // Lpix^3 / N^3
    const float TWOPI2 = 19.739208802178716f;        // 2*pi^2
    float local = 0.f;
    int ln = 0;
    for (int i = tid; i < NBATCH * KBINS; i += 256) {
        int bin = i % KBINS;
        int c = g_CNT[bin];
        if (c > 0) {
            float cf = (float)c;
            float kc = g_kcent[bin];
            float kc3 = kc * kc * kc;
            float sp = (float)g_SP[i] * PKF;
            float st = (float)g_ST[i] * PKF;
            float dp = (sp / cf) * kc3 / TWOPI2;
            float dt = (st / cf) * kc3 / TWOPI2;
            local += fabsf(log10f(dt) - log10f(dp));
            ln++;
        }
    }
    red[tid] = local; redn[tid] = ln;
    __syncthreads();
    for (int s = 128; s > 0; s >>= 1) {
        if (tid < s) { red[tid] += red[tid + s]; redn[tid] += redn[tid + s]; }
        __syncthreads();
    }
    if (tid == 0) out[0] = red[0] / (float)redn[0];
}

// ---------------------------------------------------------------------------
extern "C" void kernel_launch(void* const* d_in, const int* in_sizes, int n_in,
                              void* d_out, int out_size) {
    const float* pred = (const float*)d_in[0];
    const float* targ = (const float*)d_in[1];
    float* out = (float*)d_out;

    const int SMEM_PLANE = 2 * NSIDE * PITCH1 * (int)sizeof(float);  // 132096 B
    cudaFuncSetAttribute(k_fft_zy, cudaFuncAttributeMaxDynamicSharedMemorySize,
                         SMEM_PLANE);
    cudaFuncSetAttribute(k_fft_x_bin, cudaFuncAttributeMaxDynamicSharedMemorySize,
                         SMEM_PLANE);

    k_setup<<<1, 256>>>();
    k_fft_zy<<<dim3(NSIDE, NBATCH), 512, SMEM_PLANE>>>(pred, targ);
    k_fft_x_bin<<<dim3(NSIDE, NBATCH), 512, SMEM_PLANE>>>();
    k_final<<<1, 256>>>(out);
}

// round 13
// speedup vs baseline: 2.5248x; 1.6424x over previous
#include <cuda_runtime.h>
#include <cuda_bf16.h>
#include <math.h>

// ---------------------------------------------------------------------------
// dsq_loss: loss = nanmean |log10(Dsq(target)) - log10(Dsq(pred))|
//
// Pipeline (graph-capturable, no allocations):
//   k_fft_zy    : [block(0,0) also runs fp64 numpy-exact binning setup]
//                 Z = pred + i*target; fused z-FFT + y-FFT per x-slice
//   k_fft_x_bin : x-FFT on mirror-closed (y-pair, z-half) planes + in-shared
//                 Hermitian split + run-length radial binning (pair-once, w=2)
//   k_final     : replicate reference fp32 formula + nanmean
// ---------------------------------------------------------------------------

#define NSIDE 128
#define NMODES (128*128*128)
#define NBATCH 8
#define KBINS 100
#define MMAX 12288                  // 3*64^2
#define PITCH1 129                  // float2 units

__device__ float2 g_vol[(size_t)NBATCH * NMODES];   // 128 MB scratch
__device__ double g_SP[NBATCH * KBINS];
__device__ double g_ST[NBATCH * KBINS];
__device__ int    g_CNT[KBINS];
__device__ unsigned char g_binm[MMAX + 1];
__device__ float  g_kcent[KBINS];

__device__ __forceinline__ int rev7(int x) {
    return (int)(__brev((unsigned)x) >> 25);
}

// radix-2 DIF butterfly: a <- a+b ; b <- (a-b)*w
__device__ __forceinline__ void bfly(float& ar, float& ai, float& br, float& bi,
                                     float wr, float wi) {
    float ur = ar, ui = ai;
    ar = ur + br; ai = ui + bi;
    float dr = ur - br, di = ui - bi;
    br = dr * wr - di * wi;
    bi = dr * wi + di * wr;
}

// full 16-point DIF in registers, constant twiddles
__device__ __forceinline__ void fft16(float xr[16], float xi[16]) {
    const float C1 = 0.92387953251128674f;
    const float S1 = 0.38268343236508978f;
    const float C2 = 0.70710678118654752f;
    const float W16r[8] = {1.f,  C1,  C2,  S1, 0.f, -S1, -C2, -C1};
    const float W16i[8] = {0.f, -S1, -C2, -C1, -1.f, -C1, -C2, -S1};
#pragma unroll
    for (int j = 0; j < 8; j++)
        bfly(xr[j], xi[j], xr[j + 8], xi[j + 8], W16r[j], W16i[j]);
    const float W8r[4] = {1.f,  C2, 0.f, -C2};
    const float W8i[4] = {0.f, -C2, -1.f, -C2};
#pragma unroll
    for (int g = 0; g < 16; g += 8)
#pragma unroll
        for (int j = 0; j < 4; j++)
            bfly(xr[g + j], xi[g + j], xr[g + j + 4], xi[g + j + 4], W8r[j], W8i[j]);
#pragma unroll
    for (int g = 0; g < 16; g += 4) {
        bfly(xr[g],     xi[g],     xr[g + 2], xi[g + 2], 1.f,  0.f);
        bfly(xr[g + 1], xi[g + 1], xr[g + 3], xi[g + 3], 0.f, -1.f);
    }
#pragma unroll
    for (int g = 0; g < 16; g += 2)
        bfly(xr[g], xi[g], xr[g + 1], xi[g + 1], 1.f, 0.f);
}

// 128-point DIF FFT on 128 lines of interleaved float2 in shared memory.
// Element stride ES (float2 units), line stride LS. Bit-reversed output.
template <int ES, int LS>
__device__ __forceinline__ void fft_lines128(float2* sZ, const float2* w,
                                             int tid, int nt) {
    for (int s = tid; s < 2048; s += nt) {
        int line = s & 127;
        int t = s >> 7;                    // 0..15
        int base = line * LS;
        float2 v[8];
#pragma unroll
        for (int r = 0; r < 8; r++) v[r] = sZ[base + (t + 16 * r) * ES];
#pragma unroll
        for (int r = 0; r < 4; r++) {
            float2 tw = w[t + 16 * r];
            bfly(v[r].x, v[r].y, v[r + 4].x, v[r + 4].y, tw.x, tw.y);
        }
#pragma unroll
        for (int q = 0; q < 8; q += 4)
#pragma unroll
            for (int r = 0; r < 2; r++) {
                float2 tw = w[2 * (t + 16 * r)];
                bfly(v[q + r].x, v[q + r].y, v[q + r + 2].x, v[q + r + 2].y,
                     tw.x, tw.y);
            }
        {
            float2 tw = w[4 * t];
#pragma unroll
            for (int q = 0; q < 8; q += 2)
                bfly(v[q].x, v[q].y, v[q + 1].x, v[q + 1].y, tw.x, tw.y);
        }
#pragma unroll
        for (int r = 0; r < 8; r++) sZ[base + (t + 16 * r) * ES] = v[r];
    }
    __syncthreads();
    for (int s = tid; s < 1024; s += nt) {
        int line = s & 127;
        int blk = s >> 7;                  // 0..7
        int base = line * LS + blk * 16 * ES;
        float xr[16], xi[16];
#pragma unroll
        for (int j = 0; j < 16; j++) {
            float2 q = sZ[base + j * ES];
            xr[j] = q.x; xi[j] = q.y;
        }
        fft16(xr, xi);
#pragma unroll
        for (int j = 0; j < 16; j++)
            sZ[base + j * ES] = make_float2(xr[j], xi[j]);
    }
    __syncthreads();
}

// ---------------------------------------------------------------------------
// Kernel 1: plane (y,z) of Z = pred + i*target, z-FFT then y-FFT, store.
// Block (0,0) additionally runs the fp64 numpy-exact binning setup and zeroes
// the accumulators (consumed only after the kernel boundary).
// ---------------------------------------------------------------------------
__global__ __launch_bounds__(1024, 1)
void k_fft_zy(const float* __restrict__ pred, const float* __restrict__ targ) {
    extern __shared__ float2 sZ[];         // 128 * 129 float2
    __shared__ float2 sW[64];
    __shared__ double edges[KBINS + 1];
    int tid = threadIdx.x;
    int x = blockIdx.x, b = blockIdx.y;

    if (x == 0 && b == 0) {                // fp64 setup, hidden under 1023 peers
        const double TWO_PI = 6.283185307179586476925286766559;
        double val = 1.0 / 384.0;
        double k1  = __dmul_rn(TWO_PI, __dmul_rn(1.0, val));
        double csq = __dmul_rn(k1, k1);
        double kmin = sqrt(csq);
        double k64 = __dmul_rn(TWO_PI, __dmul_rn(64.0, val));
        double q64 = __dmul_rn(k64, k64);
        double kmax = sqrt(__dadd_rn(__dadd_rn(q64, q64), q64));
        double step = __dmul_rn(__dadd_rn(kmax, -kmin), 1.0) / 100.0;
        if (tid <= KBINS) {
            edges[tid] = (tid == KBINS) ? kmax
                        : __dadd_rn(__dmul_rn((double)tid, step), kmin);
        }
        __syncthreads();
        if (tid < KBINS)
            g_kcent[tid] = (float)(0.5 * __dadd_rn(edges[tid], edges[tid + 1]));
        for (int m = tid; m <= MMAX; m += 1024) {
            unsigned char bm;
            if (m == 0) bm = 255;
            else {
                double km = sqrt(__dmul_rn((double)m, csq));
                int lo = 0, hi = KBINS + 1;        // searchsorted right
                while (lo < hi) {
                    int mid = (lo + hi) >> 1;
                    if (edges[mid] <= km) lo = mid + 1; else hi = mid;
                }
                int bin = lo - 1;
                bin = bin < 0 ? 0 : (bin > KBINS - 1 ? KBINS - 1 : bin);
                bm = (unsigned char)bin;
            }
            g_binm[m] = bm;
        }
        for (int i = tid; i < NBATCH * KBINS; i += 1024) {
            g_SP[i] = 0.0; g_ST[i] = 0.0;
        }
        if (tid < KBINS) g_CNT[tid] = 0;
    }

    if (tid < 64) {
        float s, c;
        sincospif(-(float)tid / 64.0f, &s, &c);    // exp(-2*pi*i*t/128)
        sW[tid] = make_float2(c, s);
    }
    const float* p = pred + ((size_t)b * NSIDE + x) * (NSIDE * NSIDE);
    const float* t = targ + ((size_t)b * NSIDE + x) * (NSIDE * NSIDE);
    for (int k = tid; k < 4096; k += 1024) {
        int i = k * 4;
        int y = i >> 7, z = i & 127;
        float4 pv = *(const float4*)(p + i);
        float4 tv = *(const float4*)(t + i);
        float2* row = sZ + y * PITCH1 + z;
        row[0] = make_float2(pv.x, tv.x);
        row[1] = make_float2(pv.y, tv.y);
        row[2] = make_float2(pv.z, tv.z);
        row[3] = make_float2(pv.w, tv.w);
    }
    __syncthreads();
    fft_lines128<1, PITCH1>(sZ, sW, tid, 1024);    // z
    fft_lines128<PITCH1, 1>(sZ, sW, tid, 1024);    // y
    float2* o = g_vol + ((size_t)b * NSIDE + x) * (NSIDE * NSIDE);
    for (int k = tid; k < 8192; k += 1024) {
        int i = k * 2;
        int y = i >> 7, z = i & 127;
        float2 a = sZ[y * PITCH1 + z];
        float2 c = sZ[y * PITCH1 + z + 1];
        *(float4*)(o + i) = make_float4(a.x, a.y, c.x, c.y);
    }
}

// ---------------------------------------------------------------------------
// Kernel 2 (fused): x-FFT + Hermitian split + run-length radial binning.
//
// Block = (batch, y-pair, z-half): mirror-closed 128-line plane (as proven
// in the passing round-11 kernel). Pair-once canonical rule here is in
// NATURAL frequency coords: representative has fx in (0,64) (weight 2), or
// fx in {0,64} with line l <= mirror-line pl (w=1 if l==pl else 2).
// Threads iterate fx ascending so bin(m) changes slowly -> register
// accumulation with flush-on-bin-change; warp = 32 consecutive lines at the
// same fx -> z1 and z2 shared reads are bank-conflict-free.
// ---------------------------------------------------------------------------
__global__ __launch_bounds__(1024, 1)
void k_fft_x_bin() {
    extern __shared__ float2 sZ[];         // 128 lines x 129 float2, elem = x
    __shared__ float2 sW[64];
    __shared__ int lm2[128];               // ay^2 + az^2 per line
    __shared__ int plT[128];               // mirror-partner line
    __shared__ unsigned char shB[MMAX + 1];
    __shared__ float shP[4 * KBINS], shT[4 * KBINS];
    __shared__ int shC[KBINS];

    int tid = threadIdx.x;
    int b = blockIdx.y;
    int g = blockIdx.x >> 1;               // y-group 0..63
    int h = blockIdx.x & 1;                // z-half

    int yA, yB, selfY;
    if (g == 0) { yA = 0; yB = 1; selfY = 1; }
    else {
        int hb = 31 - __clz(g) + 1;
        int r = g - (1 << (hb - 1));
        yA = (1 << hb) + r;
        yB = (1 << hb) + ((1 << hb) - 1 - r);
        selfY = 0;
    }
    int fyA = rev7(yA), fyB = rev7(yB);
    int aA = min(fyA, 128 - fyA), aB = min(fyB, 128 - fyB);
    int ay2A = aA * aA, ay2B = aB * aB;

    if (tid < 64) {
        float s, c;
        sincospif(-(float)tid / 64.0f, &s, &c);
        sW[tid] = make_float2(c, s);
    }
    if (tid < 128) {
        int l = tid;
        int yi = l >> 6, zi = l & 63;
        int sz = h * 64 + zi;
        int f = rev7(sz), az = min(f, 128 - f);
        lm2[l] = (yi ? ay2B : ay2A) + az * az;
        int sz2 = (sz == 0) ? 0 : (sz ^ ((1 << (31 - __clz(sz))) - 1));
        int pzi = sz2 - h * 64;            // mirror stays in the same half
        int pyi = selfY ? yi : (1 - yi);
        plT[l] = pyi * 64 + pzi;
    }
    for (int i = tid; i <= MMAX; i += 1024) shB[i] = g_binm[i];
    for (int i = tid; i < 4 * KBINS; i += 1024) { shP[i] = 0.f; shT[i] = 0.f; }
    if (tid < KBINS) shC[tid] = 0;

    // Load: 64-contiguous float2 runs -> float4 (2 modes / thread / iter)
    const float2* vol = g_vol + (size_t)b * NMODES;
    for (int k = tid; k < 8192; k += 1024) {
        int i = k * 2;
        int zi = i & 63;                   // even
        int yi = (i >> 6) & 1;
        int x  = i >> 7;
        int y  = yi ? yB : yA;
        float4 v = *(const float4*)(vol + ((size_t)x << 14) + (y << 7)
                                        + h * 64 + zi);
        int l = yi * 64 + zi;
        sZ[l * PITCH1 + x]       = make_float2(v.x, v.y);
        sZ[(l + 1) * PITCH1 + x] = make_float2(v.z, v.w);
    }
    __syncthreads();

    fft_lines128<1, PITCH1>(sZ, sW, tid, 1024);    // x-FFT

    // ---- binning: thread = (chunk c of 8 fx values, line l) ----
    int c = tid >> 7;                      // 0..7 -> fx = 8c..8c+7
    int l = tid & 127;
    int pl = plT[l];
    int L2 = lm2[l];
    int rep = (tid & 3) * KBINS;
    float accP = 0.f, accT = 0.f;
    int accC = 0, cur = -1;

#pragma unroll
    for (int j = 0; j < 8; j++) {
        int fx = (c << 3) + j;
        float w = 2.f;
        if (fx == 0) {                     // warp-uniform branch (c==0, j==0)
            if (l > pl) continue;          // partner line handles it
            if (l == pl) w = 1.f;
        }
        int m = fx * fx + L2;
        if (m == 0) continue;              // DC dropped
        int sx  = rev7(fx);
        int sx2 = (fx == 0) ? 0 : rev7(128 - fx);
        float2 z1 = sZ[l  * PITCH1 + sx];
        float2 z2 = sZ[pl * PITCH1 + sx2];
        float aa = z1.x * z1.x + z1.y * z1.y;
        float bb = z2.x * z2.x + z2.y * z2.y;
        float cr = z1.x * z2.x - z1.y * z2.y;      // Re(Z1*Z2)
        float hv = 0.25f * (aa + bb);
        int bin = shB[m];
        if (bin != cur) {
            if (cur >= 0) {
                atomicAdd(&shP[rep + cur], accP);
                atomicAdd(&shT[rep + cur], accT);
                if (b == 0) atomicAdd(&shC[cur], accC);
            }
            cur = bin; accP = 0.f; accT = 0.f; accC = 0;
        }
        accP += w * (hv + 0.5f * cr);
        accT += w * (hv - 0.5f * cr);
        accC += (int)w;
    }
    if (c == 7 && l <= pl) {               // fx = 64 tail (self-mirror in x)
        float w = (l == pl) ? 1.f : 2.f;
        int m = 4096 + L2;
        float2 z1 = sZ[l  * PITCH1 + 1];   // rev7(64) == 1
        float2 z2 = sZ[pl * PITCH1 + 1];
        float aa = z1.x * z1.x + z1.y * z1.y;
        float bb = z2.x * z2.x + z2.y * z2.y;
        float cr = z1.x * z2.x - z1.y * z2.y;
        float hv = 0.25f * (aa + bb);
        int bin = shB[m];
        if (bin != cur) {
            if (cur >= 0) {
                atomicAdd(&shP[rep + cur], accP);
                atomicAdd(&shT[rep + cur], accT);
                if (b == 0) atomicAdd(&shC[cur], accC);
            }
            cur = bin; accP = 0.f; accT = 0.f; accC = 0;
        }
        accP += w * (hv + 0.5f * cr);
        accT += w * (hv - 0.5f * cr);
        accC += (int)w;
    }
    if (cur >= 0) {
        atomicAdd(&shP[rep + cur], accP);
        atomicAdd(&shT[rep + cur], accT);
        if (b == 0) atomicAdd(&shC[cur], accC);
    }
    __syncthreads();

    if (tid < KBINS) {
        float p = shP[tid] + shP[KBINS + tid] + shP[2 * KBINS + tid]
                + shP[3 * KBINS + tid];
        float t = shT[tid] + shT[KBINS + tid] + shT[2 * KBINS + tid]
                + shT[3 * KBINS + tid];
        atomicAdd(&g_SP[b * KBINS + tid], (double)p);
        atomicAdd(&g_ST[b * KBINS + tid], (double)t);
        if (b == 0) atomicAdd(&g_CNT[tid], shC[tid]);
    }
}

// ---------------------------------------------------------------------------
// Final: replicate reference fp32 formula per (b, bin) and nanmean.
// ---------------------------------------------------------------------------
__global__ void k_final(float* out) {
    __shared__ float red[256];
    __shared__ int redn[256];
    int tid = threadIdx.x;
    const float PKF = 27.0f / 2097152.0f;            // Lpix^3 / N^3
    const float TWOPI2 = 19.739208802178716f;        // 2*pi^2
    float local = 0.f;
    int ln = 0;
    for (int i = tid; i < NBATCH * KBINS; i += 256) {
        int bin = i % KBINS;
        int c = g_CNT[bin];
        if (c > 0) {
            float cf = (float)c;
            float kc = g_kcent[bin];
            float kc3 = kc * kc * kc;
            float sp = (float)g_SP[i] * PKF;
            float st = (float)g_ST[i] * PKF;
            float dp = (sp / cf) * kc3 / TWOPI2;
            float dt = (st / cf) * kc3 / TWOPI2;
            local += fabsf(log10f(dt) - log10f(dp));
            ln++;
        }
    }
    red[tid] = local; redn[tid] = ln;
    __syncthreads();
    for (int s = 128; s > 0; s >>= 1) {
        if (tid < s) { red[tid] += red[tid + s]; redn[tid] += redn[tid + s]; }
        __syncthreads();
    }
    if (tid == 0) out[0] = red[0] / (float)redn[0];
}

// ---------------------------------------------------------------------------
extern "C" void kernel_launch(void* const* d_in, const int* in_sizes, int n_in,
                              void* d_out, int out_size) {
    const float* pred = (const float*)d_in[0];
    const float* targ = (const float*)d_in[1];
    float* out = (float*)d_out;

    const int SMEM_PLANE = NSIDE * PITCH1 * (int)sizeof(float2);  // 132096 B
    cudaFuncSetAttribute(k_fft_zy, cudaFuncAttributeMaxDynamicSharedMemorySize,
                         SMEM_PLANE);
    cudaFuncSetAttribute(k_fft_x_bin, cudaFuncAttributeMaxDynamicSharedMemorySize,
                         SMEM_PLANE);

    k_fft_zy<<<dim3(NSIDE, NBATCH), 1024, SMEM_PLANE>>>(pred, targ);
    k_fft_x_bin<<<dim3(NSIDE, NBATCH), 1024, SMEM_PLANE>>>();
    k_final<<<1, 256>>>(out);
}

// round 14
// speedup vs baseline: 2.6167x; 1.0364x over previous
#include <cuda_runtime.h>
#include <cuda_bf16.h>
#include <math.h>

// ---------------------------------------------------------------------------
// dsq_loss: loss = nanmean |log10(Dsq(target)) - log10(Dsq(pred))|
//
// Pipeline (graph-capturable, no allocations):
//   k_fft_zy    : [block(0,0) also runs fp64 numpy-exact binning setup]
//                 Z = pred + i*target; z-FFT phase1 reads GLOBAL directly,
//                 fused z+y FFT, y-FFT phase2 stores GLOBAL directly
//   k_fft_x_bin : x-FFT on mirror-closed (y-pair, z-half) planes + in-shared
//                 Hermitian split + run-length radial binning; batches
//                 processed in REVERSE write order for L2 reuse; the last
//                 block to finish computes the final nanmean (no k_final).
// ---------------------------------------------------------------------------

#define NSIDE 128
#define NMODES (128*128*128)
#define NBATCH 8
#define KBINS 100
#define MMAX 12288                  // 3*64^2
#define PITCH1 129                  // float2 units

__device__ float2 g_vol[(size_t)NBATCH * NMODES];   // 128 MB scratch
__device__ double g_SP[NBATCH * KBINS];
__device__ double g_ST[NBATCH * KBINS];
__device__ int    g_CNT[KBINS];
__device__ unsigned char g_binm[MMAX + 1];
__device__ float  g_kcent[KBINS];
__device__ int    g_done;

__device__ __forceinline__ int rev7(int x) {
    return (int)(__brev((unsigned)x) >> 25);
}

// radix-2 DIF butterfly: a <- a+b ; b <- (a-b)*w
__device__ __forceinline__ void bfly(float& ar, float& ai, float& br, float& bi,
                                     float wr, float wi) {
    float ur = ar, ui = ai;
    ar = ur + br; ai = ui + bi;
    float dr = ur - br, di = ui - bi;
    br = dr * wr - di * wi;
    bi = dr * wi + di * wr;
}

// full 16-point DIF in registers, constant twiddles
__device__ __forceinline__ void fft16(float xr[16], float xi[16]) {
    const float C1 = 0.92387953251128674f;
    const float S1 = 0.38268343236508978f;
    const float C2 = 0.70710678118654752f;
    const float W16r[8] = {1.f,  C1,  C2,  S1, 0.f, -S1, -C2, -C1};
    const float W16i[8] = {0.f, -S1, -C2, -C1, -1.f, -C1, -C2, -S1};
#pragma unroll
    for (int j = 0; j < 8; j++)
        bfly(xr[j], xi[j], xr[j + 8], xi[j + 8], W16r[j], W16i[j]);
    const float W8r[4] = {1.f,  C2, 0.f, -C2};
    const float W8i[4] = {0.f, -C2, -1.f, -C2};
#pragma unroll
    for (int g = 0; g < 16; g += 8)
#pragma unroll
        for (int j = 0; j < 4; j++)
            bfly(xr[g + j], xi[g + j], xr[g + j + 4], xi[g + j + 4], W8r[j], W8i[j]);
#pragma unroll
    for (int g = 0; g < 16; g += 4) {
        bfly(xr[g],     xi[g],     xr[g + 2], xi[g + 2], 1.f,  0.f);
        bfly(xr[g + 1], xi[g + 1], xr[g + 3], xi[g + 3], 0.f, -1.f);
    }
#pragma unroll
    for (int g = 0; g < 16; g += 2)
        bfly(xr[g], xi[g], xr[g + 1], xi[g + 1], 1.f, 0.f);
}

// 3 register stages (len 128,64,32) on 8 complex at positions t+16r
__device__ __forceinline__ void stages3(float2 v[8], const float2* w, int t) {
#pragma unroll
    for (int r = 0; r < 4; r++) {
        float2 tw = w[t + 16 * r];
        bfly(v[r].x, v[r].y, v[r + 4].x, v[r + 4].y, tw.x, tw.y);
    }
#pragma unroll
    for (int q = 0; q < 8; q += 4)
#pragma unroll
        for (int r = 0; r < 2; r++) {
            float2 tw = w[2 * (t + 16 * r)];
            bfly(v[q + r].x, v[q + r].y, v[q + r + 2].x, v[q + r + 2].y,
                 tw.x, tw.y);
        }
    {
        float2 tw = w[4 * t];
#pragma unroll
        for (int q = 0; q < 8; q += 2)
            bfly(v[q].x, v[q].y, v[q + 1].x, v[q + 1].y, tw.x, tw.y);
    }
}

// 128-point DIF FFT on 128 shared lines (used by x-pass). Bit-reversed output.
template <int ES, int LS>
__device__ __forceinline__ void fft_lines128(float2* sZ, const float2* w,
                                             int tid, int nt) {
    for (int s = tid; s < 2048; s += nt) {
        int line = s & 127;
        int t = s >> 7;
        int base = line * LS;
        float2 v[8];
#pragma unroll
        for (int r = 0; r < 8; r++) v[r] = sZ[base + (t + 16 * r) * ES];
        stages3(v, w, t);
#pragma unroll
        for (int r = 0; r < 8; r++) sZ[base + (t + 16 * r) * ES] = v[r];
    }
    __syncthreads();
    for (int s = tid; s < 1024; s += nt) {
        int line = s & 127;
        int blk = s >> 7;
        int base = line * LS + blk * 16 * ES;
        float xr[16], xi[16];
#pragma unroll
        for (int j = 0; j < 16; j++) {
            float2 q = sZ[base + j * ES];
            xr[j] = q.x; xi[j] = q.y;
        }
        fft16(xr, xi);
#pragma unroll
        for (int j = 0; j < 16; j++)
            sZ[base + j * ES] = make_float2(xr[j], xi[j]);
    }
    __syncthreads();
}

// ---------------------------------------------------------------------------
// Kernel 1: plane (y,z) of Z = pred + i*target, z-FFT then y-FFT, store.
// z-phase1 reads global directly; y-phase2 stores global directly.
// Block (0,0) additionally runs the fp64 numpy-exact binning setup.
// ---------------------------------------------------------------------------
__global__ __launch_bounds__(1024, 1)
void k_fft_zy(const float* __restrict__ pred, const float* __restrict__ targ) {
    extern __shared__ float2 sZ[];         // 128 * 129 float2
    __shared__ float2 sW[64];
    __shared__ double edges[KBINS + 1];
    int tid = threadIdx.x;
    int x = blockIdx.x, b = blockIdx.y;

    if (x == 0 && b == 0) {                // fp64 setup, hidden under 1023 peers
        const double TWO_PI = 6.283185307179586476925286766559;
        double val = 1.0 / 384.0;
        double k1  = __dmul_rn(TWO_PI, __dmul_rn(1.0, val));
        double csq = __dmul_rn(k1, k1);
        double kmin = sqrt(csq);
        double k64 = __dmul_rn(TWO_PI, __dmul_rn(64.0, val));
        double q64 = __dmul_rn(k64, k64);
        double kmax = sqrt(__dadd_rn(__dadd_rn(q64, q64), q64));
        double step = __dmul_rn(__dadd_rn(kmax, -kmin), 1.0) / 100.0;
        if (tid <= KBINS) {
            edges[tid] = (tid == KBINS) ? kmax
                        : __dadd_rn(__dmul_rn((double)tid, step), kmin);
        }
        __syncthreads();
        if (tid < KBINS)
            g_kcent[tid] = (float)(0.5 * __dadd_rn(edges[tid], edges[tid + 1]));
        for (int m = tid; m <= MMAX; m += 1024) {
            unsigned char bm;
            if (m == 0) bm = 255;
            else {
                double km = sqrt(__dmul_rn((double)m, csq));
                int lo = 0, hi = KBINS + 1;        // searchsorted right
                while (lo < hi) {
                    int mid = (lo + hi) >> 1;
                    if (edges[mid] <= km) lo = mid + 1; else hi = mid;
                }
                int bin = lo - 1;
                bin = bin < 0 ? 0 : (bin > KBINS - 1 ? KBINS - 1 : bin);
                bm = (unsigned char)bin;
            }
            g_binm[m] = bm;
        }
        for (int i = tid; i < NBATCH * KBINS; i += 1024) {
            g_SP[i] = 0.0; g_ST[i] = 0.0;
        }
        if (tid < KBINS) g_CNT[tid] = 0;
        if (tid == 0) g_done = 0;
    }

    if (tid < 64) {
        float s, c;
        sincospif(-(float)tid / 64.0f, &s, &c);    // exp(-2*pi*i*t/128)
        sW[tid] = make_float2(c, s);
    }
    __syncthreads();

    const float* pr0 = pred + ((size_t)b * NSIDE + x) * (NSIDE * NSIDE);
    const float* tr0 = targ + ((size_t)b * NSIDE + x) * (NSIDE * NSIDE);

    // ---- z-FFT phase 1: global -> registers -> shared ----
    // warp covers lines {L, L+16} x 16 t-values: global reads = 2x64B sectors,
    // shared write banks {L+t} U {L+16+t} = 32 distinct (pitch 129 conflict-free)
    for (int s = tid; s < 2048; s += 1024) {
        int w5 = s >> 5, lane = s & 31;
        int line = (w5 & 15) + ((w5 >> 4) << 5) + ((lane >> 4) << 4);
        int t = lane & 15;
        const float* pr = pr0 + line * 128 + t;
        const float* tr = tr0 + line * 128 + t;
        float2 v[8];
#pragma unroll
        for (int r = 0; r < 8; r++)
            v[r] = make_float2(pr[16 * r], tr[16 * r]);
        stages3(v, sW, t);
        float2* dst = sZ + line * PITCH1 + t;
#pragma unroll
        for (int r = 0; r < 8; r++) dst[16 * r] = v[r];
    }
    __syncthreads();

    // ---- z-FFT phase 2 (contiguous 16-blocks) ----
    {
        int line = tid & 127;
        int blk = tid >> 7;
        float2* base = sZ + line * PITCH1 + blk * 16;
        float xr[16], xi[16];
#pragma unroll
        for (int j = 0; j < 16; j++) { xr[j] = base[j].x; xi[j] = base[j].y; }
        fft16(xr, xi);
#pragma unroll
        for (int j = 0; j < 16; j++) base[j] = make_float2(xr[j], xi[j]);
    }
    __syncthreads();

    // ---- y-FFT phase 1 (stride PITCH1) ----
    for (int s = tid; s < 2048; s += 1024) {
        int z = s & 127;
        int t = s >> 7;                    // 0..15 over the two iterations
        float2 v[8];
#pragma unroll
        for (int r = 0; r < 8; r++) v[r] = sZ[z + (t + 16 * r) * PITCH1];
        stages3(v, sW, t);
#pragma unroll
        for (int r = 0; r < 8; r++) sZ[z + (t + 16 * r) * PITCH1] = v[r];
    }
    __syncthreads();

    // ---- y-FFT phase 2: registers -> GLOBAL (coalesced 256B per j) ----
    {
        int z = tid & 127;
        int blk = tid >> 7;
        float xr[16], xi[16];
#pragma unroll
        for (int j = 0; j < 16; j++) {
            float2 q = sZ[z + (blk * 16 + j) * PITCH1];
            xr[j] = q.x; xi[j] = q.y;
        }
        fft16(xr, xi);
        float2* o = g_vol + ((size_t)b * NSIDE + x) * (NSIDE * NSIDE);
#pragma unroll
        for (int j = 0; j < 16; j++)
            o[(blk * 16 + j) * 128 + z] = make_float2(xr[j], xi[j]);
    }
}

// ---------------------------------------------------------------------------
// Kernel 2 (fused): x-FFT + Hermitian split + run-length radial binning.
// Batches processed in reverse write order (b = 7 - blockIdx.y) so the first
// waves read zy's freshest output from L2. Last block computes the final loss.
// ---------------------------------------------------------------------------
__global__ __launch_bounds__(1024, 1)
void k_fft_x_bin(float* __restrict__ out) {
    extern __shared__ float2 sZ[];         // 128 lines x 129 float2, elem = x
    __shared__ float2 sW[64];
    __shared__ int lm2[128];               // ay^2 + az^2 per line
    __shared__ int plT[128];               // mirror-partner line
    __shared__ unsigned char shB[MMAX + 1];
    __shared__ float shP[4 * KBINS], shT[4 * KBINS];
    __shared__ int shC[KBINS];
    __shared__ int isLast;

    int tid = threadIdx.x;
    int b = (NBATCH - 1) - blockIdx.y;     // reverse order for L2 reuse
    int g = blockIdx.x >> 1;               // y-group 0..63
    int h = blockIdx.x & 1;                // z-half

    int yA, yB, selfY;
    if (g == 0) { yA = 0; yB = 1; selfY = 1; }
    else {
        int hb = 31 - __clz(g) + 1;
        int r = g - (1 << (hb - 1));
        yA = (1 << hb) + r;
        yB = (1 << hb) + ((1 << hb) - 1 - r);
        selfY = 0;
    }
    int fyA = rev7(yA), fyB = rev7(yB);
    int aA = min(fyA, 128 - fyA), aB = min(fyB, 128 - fyB);
    int ay2A = aA * aA, ay2B = aB * aB;

    if (tid < 64) {
        float s, c;
        sincospif(-(float)tid / 64.0f, &s, &c);
        sW[tid] = make_float2(c, s);
    }
    if (tid < 128) {
        int l = tid;
        int yi = l >> 6, zi = l & 63;
        int sz = h * 64 + zi;
        int f = rev7(sz), az = min(f, 128 - f);
        lm2[l] = (yi ? ay2B : ay2A) + az * az;
        int sz2 = (sz == 0) ? 0 : (sz ^ ((1 << (31 - __clz(sz))) - 1));
        int pzi = sz2 - h * 64;            // mirror stays in the same half
        int pyi = selfY ? yi : (1 - yi);
        plT[l] = pyi * 64 + pzi;
    }
    for (int i = tid; i <= MMAX; i += 1024) shB[i] = g_binm[i];
    for (int i = tid; i < 4 * KBINS; i += 1024) { shP[i] = 0.f; shT[i] = 0.f; }
    if (tid < KBINS) shC[tid] = 0;

    // Load: 64-contiguous float2 runs -> float4 (2 modes / thread / iter)
    const float2* vol = g_vol + (size_t)b * NMODES;
    for (int k = tid; k < 8192; k += 1024) {
        int i = k * 2;
        int zi = i & 63;                   // even
        int yi = (i >> 6) & 1;
        int x  = i >> 7;
        int y  = yi ? yB : yA;
        float4 v = *(const float4*)(vol + ((size_t)x << 14) + (y << 7)
                                        + h * 64 + zi);
        int l = yi * 64 + zi;
        sZ[l * PITCH1 + x]       = make_float2(v.x, v.y);
        sZ[(l + 1) * PITCH1 + x] = make_float2(v.z, v.w);
    }
    __syncthreads();

    fft_lines128<1, PITCH1>(sZ, sW, tid, 1024);    // x-FFT

    // ---- binning: thread = (chunk c of 8 fx values, line l) ----
    int c = tid >> 7;                      // 0..7 -> fx = 8c..8c+7
    int l = tid & 127;
    int pl = plT[l];
    int L2 = lm2[l];
    int rep = (tid & 3) * KBINS;
    float accP = 0.f, accT = 0.f;
    int accC = 0, cur = -1;

#pragma unroll
    for (int j = 0; j < 8; j++) {
        int fx = (c << 3) + j;
        float w = 2.f;
        if (fx == 0) {                     // warp-uniform branch (c==0, j==0)
            if (l > pl) continue;          // partner line handles it
            if (l == pl) w = 1.f;
        }
        int m = fx * fx + L2;
        if (m == 0) continue;              // DC dropped
        int sx  = rev7(fx);
        int sx2 = (fx == 0) ? 0 : rev7(128 - fx);
        float2 z1 = sZ[l  * PITCH1 + sx];
        float2 z2 = sZ[pl * PITCH1 + sx2];
        float aa = z1.x * z1.x + z1.y * z1.y;
        float bb = z2.x * z2.x + z2.y * z2.y;
        float cr = z1.x * z2.x - z1.y * z2.y;      // Re(Z1*Z2)
        float hv = 0.25f * (aa + bb);
        int bin = shB[m];
        if (bin != cur) {
            if (cur >= 0) {
                atomicAdd(&shP[rep + cur], accP);
                atomicAdd(&shT[rep + cur], accT);
                if (b == 0) atomicAdd(&shC[cur], accC);
            }
            cur = bin; accP = 0.f; accT = 0.f; accC = 0;
        }
        accP += w * (hv + 0.5f * cr);
        accT += w * (hv - 0.5f * cr);
        accC += (int)w;
    }
    if (c == 7 && l <= pl) {               // fx = 64 tail (self-mirror in x)
        float w = (l == pl) ? 1.f : 2.f;
        int m = 4096 + L2;
        float2 z1 = sZ[l  * PITCH1 + 1];   // rev7(64) == 1
        float2 z2 = sZ[pl * PITCH1 + 1];
        float aa = z1.x * z1.x + z1.y * z1.y;
        float bb = z2.x * z2.x + z2.y * z2.y;
        float cr = z1.x * z2.x - z1.y * z2.y;
        float hv = 0.25f * (aa + bb);
        int bin = shB[m];
        if (bin != cur) {
            if (cur >= 0) {
                atomicAdd(&shP[rep + cur], accP);
                atomicAdd(&shT[rep + cur], accT);
                if (b == 0) atomicAdd(&shC[cur], accC);
            }
            cur = bin; accP = 0.f; accT = 0.f; accC = 0;
        }
        accP += w * (hv + 0.5f * cr);
        accT += w * (hv - 0.5f * cr);
        accC += (int)w;
    }
    if (cur >= 0) {
        atomicAdd(&shP[rep + cur], accP);
        atomicAdd(&shT[rep + cur], accT);
        if (b == 0) atomicAdd(&shC[cur], accC);
    }
    __syncthreads();

    if (tid < KBINS) {
        float p = shP[tid] + shP[KBINS + tid] + shP[2 * KBINS + tid]
                + shP[3 * KBINS + tid];
        float t = shT[tid] + shT[KBINS + tid] + shT[2 * KBINS + tid]
                + shT[3 * KBINS + tid];
        atomicAdd(&g_SP[b * KBINS + tid], (double)p);
        atomicAdd(&g_ST[b * KBINS + tid], (double)t);
        if (b == 0) atomicAdd(&g_CNT[tid], shC[tid]);
    }

    // ---- last block computes the final loss (replaces k_final) ----
    if (tid == 0) {
        __threadfence();
        int v = atomicAdd(&g_done, 1);
        isLast = (v == (int)(gridDim.x * gridDim.y) - 1);
    }
    __syncthreads();
    if (isLast) {
        // reuse shP as the float reduction buffer, shB as int buffer space
        __shared__ float redF[1024];
        __shared__ int   redN[1024];
        const float PKF = 27.0f / 2097152.0f;        // Lpix^3 / N^3
        const float TWOPI2 = 19.739208802178716f;    // 2*pi^2
        float local = 0.f;
        int ln = 0;
        if (tid < NBATCH * KBINS) {
            int bin = tid % KBINS;
            int cnt = g_CNT[bin];
            if (cnt > 0) {
                float cf = (float)cnt;
                float kc = g_kcent[bin];
                float kc3 = kc * kc * kc;
                float sp = (float)g_SP[tid] * PKF;
                float st = (float)g_ST[tid] * PKF;
                float dp = (sp / cf) * kc3 / TWOPI2;
                float dt = (st / cf) * kc3 / TWOPI2;
                local = fabsf(log10f(dt) - log10f(dp));
                ln = 1;
            }
        }
        redF[tid] = local; redN[tid] = ln;
        __syncthreads();
        for (int s = 512; s > 0; s >>= 1) {
            if (tid < s) { redF[tid] += redF[tid + s]; redN[tid] += redN[tid + s]; }
            __syncthreads();
        }
        if (tid == 0) out[0] = redF[0] / (float)redN[0];
    }
}

// ---------------------------------------------------------------------------
extern "C" void kernel_launch(void* const* d_in, const int* in_sizes, int n_in,
                              void* d_out, int out_size) {
    const float* pred = (const float*)d_in[0];
    const float* targ = (const float*)d_in[1];
    float* out = (float*)d_out;

    const int SMEM_PLANE = NSIDE * PITCH1 * (int)sizeof(float2);  // 132096 B
    cudaFuncSetAttribute(k_fft_zy, cudaFuncAttributeMaxDynamicSharedMemorySize,
                         SMEM_PLANE);
    cudaFuncSetAttribute(k_fft_x_bin, cudaFuncAttributeMaxDynamicSharedMemorySize,
                         SMEM_PLANE);

    k_fft_zy<<<dim3(NSIDE, NBATCH), 1024, SMEM_PLANE>>>(pred, targ);
    k_fft_x_bin<<<dim3(NSIDE, NBATCH), 1024, SMEM_PLANE>>>(out);
}

// round 17
// speedup vs baseline: 2.9190x; 1.1155x over previous
#include <cuda_runtime.h>
#include <cuda_bf16.h>
#include <math.h>

// ---------------------------------------------------------------------------
// dsq_loss: loss = nanmean |log10(Dsq(target)) - log10(Dsq(pred))|
//
// Pipeline (graph-capturable, no allocations):
//   k_fft_zy    : [block(0,0) also runs fp64 numpy-exact binning setup]
//                 Z = pred + i*target; z-FFT phase1 reads GLOBAL directly,
//                 fused z+y FFT, y-FFT phase2 stores GLOBAL directly
//   k_fft_x_bin : x-FFT on mirror-closed (y-pair, z-SET) 64-line planes
//                 (66KB -> 2 blocks/SM for barrier-latency overlap) +
//                 in-shared Hermitian split + run-length radial binning;
//                 last block computes the final nanmean.
// ---------------------------------------------------------------------------

#define NSIDE 128
#define NMODES (128*128*128)
#define NBATCH 8
#define KBINS 100
#define MMAX 12288                  // 3*64^2
#define PITCH1 129                  // float2 units

__device__ float2 g_vol[(size_t)NBATCH * NMODES];   // 128 MB scratch
__device__ double g_SP[NBATCH * KBINS];
__device__ double g_ST[NBATCH * KBINS];
__device__ int    g_CNT[KBINS];
__device__ unsigned char g_binm[MMAX + 1];
__device__ float  g_kcent[KBINS];
__device__ int    g_done;

__device__ __forceinline__ int rev7(int x) {
    return (int)(__brev((unsigned)x) >> 25);
}

// radix-2 DIF butterfly: a <- a+b ; b <- (a-b)*w
__device__ __forceinline__ void bfly(float& ar, float& ai, float& br, float& bi,
                                     float wr, float wi) {
    float ur = ar, ui = ai;
    ar = ur + br; ai = ui + bi;
    float dr = ur - br, di = ui - bi;
    br = dr * wr - di * wi;
    bi = dr * wi + di * wr;
}

// full 16-point DIF in registers, constant twiddles
__device__ __forceinline__ void fft16(float xr[16], float xi[16]) {
    const float C1 = 0.92387953251128674f;
    const float S1 = 0.38268343236508978f;
    const float C2 = 0.70710678118654752f;
    const float W16r[8] = {1.f,  C1,  C2,  S1, 0.f, -S1, -C2, -C1};
    const float W16i[8] = {0.f, -S1, -C2, -C1, -1.f, -C1, -C2, -S1};
#pragma unroll
    for (int j = 0; j < 8; j++)
        bfly(xr[j], xi[j], xr[j + 8], xi[j + 8], W16r[j], W16i[j]);
    const float W8r[4] = {1.f,  C2, 0.f, -C2};
    const float W8i[4] = {0.f, -C2, -1.f, -C2};
#pragma unroll
    for (int g = 0; g < 16; g += 8)
#pragma unroll
        for (int j = 0; j < 4; j++)
            bfly(xr[g + j], xi[g + j], xr[g + j + 4], xi[g + j + 4], W8r[j], W8i[j]);
#pragma unroll
    for (int g = 0; g < 16; g += 4) {
        bfly(xr[g],     xi[g],     xr[g + 2], xi[g + 2], 1.f,  0.f);
        bfly(xr[g + 1], xi[g + 1], xr[g + 3], xi[g + 3], 0.f, -1.f);
    }
#pragma unroll
    for (int g = 0; g < 16; g += 2)
        bfly(xr[g], xi[g], xr[g + 1], xi[g + 1], 1.f, 0.f);
}

// 3 register stages (len 128,64,32) on 8 complex at positions t+16r
__device__ __forceinline__ void stages3(float2 v[8], const float2* w, int t) {
#pragma unroll
    for (int r = 0; r < 4; r++) {
        float2 tw = w[t + 16 * r];
        bfly(v[r].x, v[r].y, v[r + 4].x, v[r + 4].y, tw.x, tw.y);
    }
#pragma unroll
    for (int q = 0; q < 8; q += 4)
#pragma unroll
        for (int r = 0; r < 2; r++) {
            float2 tw = w[2 * (t + 16 * r)];
            bfly(v[q + r].x, v[q + r].y, v[q + r + 2].x, v[q + r + 2].y,
                 tw.x, tw.y);
        }
    {
        float2 tw = w[4 * t];
#pragma unroll
        for (int q = 0; q < 8; q += 2)
            bfly(v[q].x, v[q].y, v[q + 1].x, v[q + 1].y, tw.x, tw.y);
    }
}

// ---------------------------------------------------------------------------
// Kernel 1: plane (y,z) of Z = pred + i*target, z-FFT then y-FFT, store.
// z-phase1 reads global directly; y-phase2 stores global directly.
// Block (0,0) additionally runs the fp64 numpy-exact binning setup.
// ---------------------------------------------------------------------------
__global__ __launch_bounds__(1024, 1)
void k_fft_zy(const float* __restrict__ pred, const float* __restrict__ targ) {
    extern __shared__ float2 sZ[];         // 128 * 129 float2
    __shared__ float2 sW[64];
    __shared__ double edges[KBINS + 1];
    int tid = threadIdx.x;
    int x = blockIdx.x, b = blockIdx.y;

    if (x == 0 && b == 0) {                // fp64 setup, hidden under 1023 peers
        const double TWO_PI = 6.283185307179586476925286766559;
        double val = 1.0 / 384.0;
        double k1  = __dmul_rn(TWO_PI, __dmul_rn(1.0, val));
        double csq = __dmul_rn(k1, k1);
        double kmin = sqrt(csq);
        double k64 = __dmul_rn(TWO_PI, __dmul_rn(64.0, val));
        double q64 = __dmul_rn(k64, k64);
        double kmax = sqrt(__dadd_rn(__dadd_rn(q64, q64), q64));
        double step = __dmul_rn(__dadd_rn(kmax, -kmin), 1.0) / 100.0;
        if (tid <= KBINS) {
            edges[tid] = (tid == KBINS) ? kmax
                        : __dadd_rn(__dmul_rn((double)tid, step), kmin);
        }
        __syncthreads();
        if (tid < KBINS)
            g_kcent[tid] = (float)(0.5 * __dadd_rn(edges[tid], edges[tid + 1]));
        for (int m = tid; m <= MMAX; m += 1024) {
            unsigned char bm;
            if (m == 0) bm = 255;
            else {
                double km = sqrt(__dmul_rn((double)m, csq));
                int lo = 0, hi = KBINS + 1;        // searchsorted right
                while (lo < hi) {
                    int mid = (lo + hi) >> 1;
                    if (edges[mid] <= km) lo = mid + 1; else hi = mid;
                }
                int bin = lo - 1;
                bin = bin < 0 ? 0 : (bin > KBINS - 1 ? KBINS - 1 : bin);
                bm = (unsigned char)bin;
            }
            g_binm[m] = bm;
        }
        for (int i = tid; i < NBATCH * KBINS; i += 1024) {
            g_SP[i] = 0.0; g_ST[i] = 0.0;
        }
        if (tid < KBINS) g_CNT[tid] = 0;
        if (tid == 0) g_done = 0;
    }

    if (tid < 64) {
        float s, c;
        sincospif(-(float)tid / 64.0f, &s, &c);    // exp(-2*pi*i*t/128)
        sW[tid] = make_float2(c, s);
    }
    __syncthreads();

    const float* pr0 = pred + ((size_t)b * NSIDE + x) * (NSIDE * NSIDE);
    const float* tr0 = targ + ((size_t)b * NSIDE + x) * (NSIDE * NSIDE);

    // ---- z-FFT phase 1: global -> registers -> shared ----
    for (int s = tid; s < 2048; s += 1024) {
        int w5 = s >> 5, lane = s & 31;
        int line = (w5 & 15) + ((w5 >> 4) << 5) + ((lane >> 4) << 4);
        int t = lane & 15;
        const float* pr = pr0 + line * 128 + t;
        const float* tr = tr0 + line * 128 + t;
        float2 v[8];
#pragma unroll
        for (int r = 0; r < 8; r++)
            v[r] = make_float2(pr[16 * r], tr[16 * r]);
        stages3(v, sW, t);
        float2* dst = sZ + line * PITCH1 + t;
#pragma unroll
        for (int r = 0; r < 8; r++) dst[16 * r] = v[r];
    }
    __syncthreads();

    // ---- z-FFT phase 2 (contiguous 16-blocks) ----
    {
        int line = tid & 127;
        int blk = tid >> 7;
        float2* base = sZ + line * PITCH1 + blk * 16;
        float xr[16], xi[16];
#pragma unroll
        for (int j = 0; j < 16; j++) { xr[j] = base[j].x; xi[j] = base[j].y; }
        fft16(xr, xi);
#pragma unroll
        for (int j = 0; j < 16; j++) base[j] = make_float2(xr[j], xi[j]);
    }
    __syncthreads();

    // ---- y-FFT phase 1 (stride PITCH1) ----
    for (int s = tid; s < 2048; s += 1024) {
        int z = s & 127;
        int t = s >> 7;
        float2 v[8];
#pragma unroll
        for (int r = 0; r < 8; r++) v[r] = sZ[z + (t + 16 * r) * PITCH1];
        stages3(v, sW, t);
#pragma unroll
        for (int r = 0; r < 8; r++) sZ[z + (t + 16 * r) * PITCH1] = v[r];
    }
    __syncthreads();

    // ---- y-FFT phase 2: registers -> GLOBAL (coalesced 256B per j) ----
    {
        int z = tid & 127;
        int blk = tid >> 7;
        float xr[16], xi[16];
#pragma unroll
        for (int j = 0; j < 16; j++) {
            float2 q = sZ[z + (blk * 16 + j) * PITCH1];
            xr[j] = q.x; xi[j] = q.y;
        }
        fft16(xr, xi);
        float2* o = g_vol + ((size_t)b * NSIDE + x) * (NSIDE * NSIDE);
#pragma unroll
        for (int j = 0; j < 16; j++)
            o[(blk * 16 + j) * 128 + z] = make_float2(xr[j], xi[j]);
    }
}

// ---------------------------------------------------------------------------
// Kernel 2 (fused): x-FFT + Hermitian split + run-length radial binning.
//
// Block = (batch, y-pair g, mirror-closed z-set of 32 stored-z): 64 lines,
// 66 KB plane -> 2 blocks/SM (512 thr each) so barrier bubbles of one block
// are hidden by the other. z-sets (stored coords, each closed under
// sz -> sz ^ (2^ceil(log2 sz) - 1)):
//   set0 [0,32)   set1 [32,64)   set2 [64,80)+[112,128)   set3 [80,112)
// Batches in reverse write order for L2 reuse. Last block computes the loss.
// ---------------------------------------------------------------------------
__global__ __launch_bounds__(512, 2)
void k_fft_x_bin(float* __restrict__ out) {
    extern __shared__ float2 sZ[];         // 64 lines x 129 float2, elem = x
    __shared__ float2 sW[64];
    __shared__ int lm2[64];                // ay^2 + az^2 per line
    __shared__ int plT[64];                // mirror-partner line
    __shared__ unsigned char shB[MMAX + 1];
    __shared__ float shP[4 * KBINS], shT[4 * KBINS];
    __shared__ int shC[KBINS];
    __shared__ int isLast;
    __shared__ float redF[512];
    __shared__ int   redN[512];

    int tid = threadIdx.x;
    int b = (NBATCH - 1) - blockIdx.y;     // reverse order for L2 reuse
    int g = blockIdx.x >> 2;               // y-group 0..63
    int zset = blockIdx.x & 3;             // which mirror-closed z-set

    int yA, yB, selfY;
    if (g == 0) { yA = 0; yB = 1; selfY = 1; }
    else {
        int hb = 31 - __clz(g) + 1;
        int r = g - (1 << (hb - 1));
        yA = (1 << hb) + r;
        yB = (1 << hb) + ((1 << hb) - 1 - r);
        selfY = 0;
    }
    int fyA = rev7(yA), fyB = rev7(yB);
    int aA = min(fyA, 128 - fyA), aB = min(fyB, 128 - fyB);
    int ay2A = aA * aA, ay2B = aB * aB;

    const int szBaseT[4] = {0, 32, 64, 80};
    int szBase = szBaseT[zset];
    int szAdd16 = (zset == 2) ? 32 : 0;    // set2 second half jumps to 112

    if (tid < 64) {
        float s, c;
        sincospif(-(float)tid / 64.0f, &s, &c);
        sW[tid] = make_float2(c, s);
    }
    if (tid < 64) {
        int l = tid;
        int yi = l >> 5, zi = l & 31;
        int sz = szBase + zi + ((zi >= 16) ? szAdd16 : 0);
        int f = rev7(sz), az = min(f, 128 - f);
        lm2[l] = (yi ? ay2B : ay2A) + az * az;
        int sz2 = (sz == 0) ? 0 : (sz ^ ((1 << (31 - __clz(sz))) - 1));
        int pzi = (sz2 >= szBase + 16 + szAdd16) ? (sz2 - szBase - szAdd16)
                                                 : (sz2 - szBase);
        int pyi = selfY ? yi : (1 - yi);
        plT[l] = pyi * 32 + pzi;
    }
    for (int i = tid; i <= MMAX; i += 512) shB[i] = g_binm[i];
    for (int i = tid; i < 4 * KBINS; i += 512) { shP[i] = 0.f; shT[i] = 0.f; }
    if (tid < KBINS) shC[tid] = 0;

    // Load: contiguous float2 runs (>=16) -> float4 (2 modes / thread / iter)
    const float2* vol = g_vol + (size_t)b * NMODES;
    for (int k = tid; k < 4096; k += 512) {
        int i = k * 2;
        int zi = i & 31;                   // even; never straddles zi=16
        int yi = (i >> 5) & 1;
        int x  = i >> 6;
        int y  = yi ? yB : yA;
        int sz = szBase + zi + ((zi >= 16) ? szAdd16 : 0);
        float4 v = *(const float4*)(vol + ((size_t)x << 14) + (y << 7) + sz);
        int l = yi * 32 + zi;
        sZ[l * PITCH1 + x]       = make_float2(v.x, v.y);
        sZ[(l + 1) * PITCH1 + x] = make_float2(v.z, v.w);
    }
    __syncthreads();

    // ---- x-FFT on 64 lines ----
    for (int s = tid; s < 1024; s += 512) {
        int line = s & 63;
        int t = s >> 6;
        float2* base = sZ + line * PITCH1;
        float2 v[8];
#pragma unroll
        for (int r = 0; r < 8; r++) v[r] = base[t + 16 * r];
        stages3(v, sW, t);
#pragma unroll
        for (int r = 0; r < 8; r++) base[t + 16 * r] = v[r];
    }
    __syncthreads();
    {
        int line = tid & 63;
        int blk = tid >> 6;
        float2* base = sZ + line * PITCH1 + blk * 16;
        float xr[16], xi[16];
#pragma unroll
        for (int j = 0; j < 16; j++) { xr[j] = base[j].x; xi[j] = base[j].y; }
        fft16(xr, xi);
#pragma unroll
        for (int j = 0; j < 16; j++) base[j] = make_float2(xr[j], xi[j]);
    }
    __syncthreads();

    // ---- binning: thread = (chunk c of 8 fx values, line l) ----
    int c = tid >> 6;                      // 0..7 -> fx = 8c..8c+7
    int l = tid & 63;
    int pl = plT[l];
    int L2 = lm2[l];
    int rep = (tid & 3) * KBINS;
    float accP = 0.f, accT = 0.f;
    int accC = 0, cur = -1;

#pragma unroll
    for (int j = 0; j < 8; j++) {
        int fx = (c << 3) + j;
        float w = 2.f;
        if (fx == 0) {                     // warp-uniform branch (c==0, j==0)
            if (l > pl) continue;          // partner line handles it
            if (l == pl) w = 1.f;
        }
        int m = fx * fx + L2;
        if (m == 0) continue;              // DC dropped
        int sx  = rev7(fx);
        int sx2 = (fx == 0) ? 0 : rev7(128 - fx);
        float2 z1 = sZ[l  * PITCH1 + sx];
        float2 z2 = sZ[pl * PITCH1 + sx2];
        float aa = z1.x * z1.x + z1.y * z1.y;
        float bb = z2.x * z2.x + z2.y * z2.y;
        float cr = z1.x * z2.x - z1.y * z2.y;      // Re(Z1*Z2)
        float hv = 0.25f * (aa + bb);
        int bin = shB[m];
        if (bin != cur) {
            if (cur >= 0) {
                atomicAdd(&shP[rep + cur], accP);
                atomicAdd(&shT[rep + cur], accT);
                if (b == 0) atomicAdd(&shC[cur], accC);
            }
            cur = bin; accP = 0.f; accT = 0.f; accC = 0;
        }
        accP += w * (hv + 0.5f * cr);
        accT += w * (hv - 0.5f * cr);
        accC += (int)w;
    }
    if (c == 7 && l <= pl) {               // fx = 64 tail (self-mirror in x)
        float w = (l == pl) ? 1.f : 2.f;
        int m = 4096 + L2;
        float2 z1 = sZ[l  * PITCH1 + 1];   // rev7(64) == 1
        float2 z2 = sZ[pl * PITCH1 + 1];
        float aa = z1.x * z1.x + z1.y * z1.y;
        float bb = z2.x * z2.x + z2.y * z2.y;
        float cr = z1.x * z2.x - z1.y * z2.y;
        float hv = 0.25f * (aa + bb);
        int bin = shB[m];
        if (bin != cur) {
            if (cur >= 0) {
                atomicAdd(&shP[rep + cur], accP);
                atomicAdd(&shT[rep + cur], accT);
                if (b == 0) atomicAdd(&shC[cur], accC);
            }
            cur = bin; accP = 0.f; accT = 0.f; accC = 0;
        }
        accP += w * (hv + 0.5f * cr);
        accT += w * (hv - 0.5f * cr);
        accC += (int)w;
    }
    if (cur >= 0) {
        atomicAdd(&shP[rep + cur], accP);
        atomicAdd(&shT[rep + cur], accT);
        if (b == 0) atomicAdd(&shC[cur], accC);
    }
    __syncthreads();

    if (tid < KBINS) {
        float p = shP[tid] + shP[KBINS + tid] + shP[2 * KBINS + tid]
                + shP[3 * KBINS + tid];
        float t = shT[tid] + shT[KBINS + tid] + shT[2 * KBINS + tid]
                + shT[3 * KBINS + tid];
        atomicAdd(&g_SP[b * KBINS + tid], (double)p);
        atomicAdd(&g_ST[b * KBINS + tid], (double)t);
        if (b == 0) atomicAdd(&g_CNT[tid], shC[tid]);
    }

    // ---- last block computes the final loss (threadFenceReduction pattern):
    // every thread fences its global atomics, barrier, THEN tid0 takes ticket.
    __threadfence();
    __syncthreads();
    if (tid == 0) {
        int v = atomicAdd(&g_done, 1);
        isLast = (v == (int)(gridDim.x * gridDim.y) - 1);
    }
    __syncthreads();
    if (isLast) {
        __threadfence();
        const float PKF = 27.0f / 2097152.0f;        // Lpix^3 / N^3
        const float TWOPI2 = 19.739208802178716f;    // 2*pi^2
        float local = 0.f;
        int ln = 0;
        for (int i = tid; i < NBATCH * KBINS; i += 512) {
            int bin = i % KBINS;
            int cnt = g_CNT[bin];
            if (cnt > 0) {
                float cf = (float)cnt;
                float kc = g_kcent[bin];
                float kc3 = kc * kc * kc;
                float sp = (float)g_SP[i] * PKF;
                float st = (float)g_ST[i] * PKF;
                float dp = (sp / cf) * kc3 / TWOPI2;
                float dt = (st / cf) * kc3 / TWOPI2;
                local += fabsf(log10f(dt) - log10f(dp));
                ln++;
            }
        }
        redF[tid] = local; redN[tid] = ln;
        __syncthreads();
        for (int s = 256; s > 0; s >>= 1) {
            if (tid < s) { redF[tid] += redF[tid + s]; redN[tid] += redN[tid + s]; }
            __syncthreads();
        }
        if (tid == 0) out[0] = redF[0] / (float)redN[0];
    }
}

// ---------------------------------------------------------------------------
extern "C" void kernel_launch(void* const* d_in, const int* in_sizes, int n_in,
                              void* d_out, int out_size) {
    const float* pred = (const float*)d_in[0];
    const float* targ = (const float*)d_in[1];
    float* out = (float*)d_out;

    const int SMEM_PLANE = NSIDE * PITCH1 * (int)sizeof(float2);     // 132096 B
    const int SMEM_HALF  = 64 * PITCH1 * (int)sizeof(float2);        //  66048 B
    cudaFuncSetAttribute(k_fft_zy, cudaFuncAttributeMaxDynamicSharedMemorySize,
                         SMEM_PLANE);
    cudaFuncSetAttribute(k_fft_x_bin, cudaFuncAttributeMaxDynamicSharedMemorySize,
                         SMEM_HALF);

    k_fft_zy<<<dim3(NSIDE, NBATCH), 1024, SMEM_PLANE>>>(pred, targ);
    k_fft_x_bin<<<dim3(256, NBATCH), 512, SMEM_HALF>>>(out);
}